// round 6
// baseline (speedup 1.0000x reference)
#include <cuda_runtime.h>
#include <math.h>

// ---------------------------------------------------------------------------
// Problem shape (fixed by setup_inputs): B=8, Cin=Cout=64, H=W=256
// ---------------------------------------------------------------------------
#define BB   8
#define CC   64
#define HH   256
#define WW   256
#define HW   65536           // H*W
#define NTOT 33554432        // B*C*H*W

// Scratch: conv+bias output y (pre-BN), 128 MiB
static __device__ float  g_y[NTOT];
static __device__ double g_sum[CC], g_sumsq[CC];
static __device__ float  g_scale[CC], g_shift[CC];
static __device__ float  g_K5[25], g_D3[9];

// ---------------------------------------------------------------------------
// Prep: zero stats; build D3 = fx - fy (3x3) and K5 = fx*fx + fy*fy (5x5,
// linear autocorrelation-style convolution of each filter with itself).
// ---------------------------------------------------------------------------
__global__ void prep_kernel(const float* __restrict__ fx,
                            const float* __restrict__ fy) {
    int t = threadIdx.x;
    if (t < CC) { g_sum[t] = 0.0; g_sumsq[t] = 0.0; }
    if (t < 9)  g_D3[t] = fx[t] - fy[t];
    if (t < 25) {
        int m = t / 5, n = t % 5;
        float s = 0.f;
        for (int k = 0; k < 3; k++)
            for (int l = 0; l < 3; l++) {
                int mk = m - k, nl = n - l;
                if (mk >= 0 && mk < 3 && nl >= 0 && nl < 3)
                    s += fx[k*3 + l] * fx[mk*3 + nl]
                       + fy[k*3 + l] * fy[mk*3 + nl];
            }
        g_K5[t] = s;
    }
}

// ---------------------------------------------------------------------------
// Conv 3x3 (zero pad 1) + bias, fused per-channel sum / sumsq for BN.
// Block: 256 threads (32,8). Tile: 32x32 spatial x 8 out-channels, one batch.
// Grid: (W/32, H/32, B*8). Each thread: 4 rows (stride 8) x 8 c_out = 32 acc.
// ---------------------------------------------------------------------------
__global__ void __launch_bounds__(256, 2) conv_kernel(
    const float* __restrict__ in,     // [B, 64, 256, 256]
    const float* __restrict__ wgt,    // [64, 64, 3, 3]
    const float* __restrict__ bias)   // [64]
{
    __shared__ float s_in[34 * 36];   // 34x34 tile, row-padded to 36
    __shared__ float s_w[72];         // 8 c_out x 9 taps
    __shared__ float s_red[8][8][2];  // [warp][c_out][sum,sumsq]

    const int tx  = threadIdx.x;               // 0..31  (w within tile)
    const int ty  = threadIdx.y;               // 0..7
    const int tid = ty * 32 + tx;
    const int h0  = blockIdx.y * 32;
    const int w0  = blockIdx.x * 32;
    const int b   = blockIdx.z >> 3;
    const int c0  = (blockIdx.z & 7) * 8;

    float acc[4][8];
    #pragma unroll
    for (int rr = 0; rr < 4; rr++)
        #pragma unroll
        for (int co = 0; co < 8; co++) acc[rr][co] = 0.f;

    const float* inb = in + (size_t)b * (CC * HW);

    for (int ci = 0; ci < CC; ci++) {
        // cooperative load of 34x34 input tile (zero-padded at image borders)
        const float* inc = inb + ci * HW;
        #pragma unroll
        for (int idx = tid; idx < 34 * 34; idx += 256) {
            int r  = idx / 34;
            int cc = idx - r * 34;
            int gh = h0 - 1 + r;
            int gw = w0 - 1 + cc;
            float v = 0.f;
            if ((unsigned)gh < 256u && (unsigned)gw < 256u)
                v = inc[gh * 256 + gw];
            s_in[r * 36 + cc] = v;
        }
        if (tid < 72) {
            int co = tid / 9, k = tid - co * 9;
            s_w[tid] = wgt[(size_t)(c0 + co) * 576 + ci * 9 + k];
        }
        __syncthreads();

        // gather this thread's 4 input windows (3x3 each) into registers
        float a[4][9];
        #pragma unroll
        for (int rr = 0; rr < 4; rr++) {
            const int r = ty + rr * 8;
            #pragma unroll
            for (int i = 0; i < 3; i++)
                #pragma unroll
                for (int j = 0; j < 3; j++)
                    a[rr][i * 3 + j] = s_in[(r + i) * 36 + tx + j];
        }
        // weight-hoisted accumulation: 9 LDS per c_out, 36 FFMAs reuse them
        #pragma unroll
        for (int co = 0; co < 8; co++) {
            float w[9];
            #pragma unroll
            for (int k = 0; k < 9; k++) w[k] = s_w[co * 9 + k];
            #pragma unroll
            for (int rr = 0; rr < 4; rr++) {
                float s = acc[rr][co];
                #pragma unroll
                for (int k = 0; k < 9; k++) s = fmaf(a[rr][k], w[k], s);
                acc[rr][co] = s;
            }
        }
        __syncthreads();
    }

    // epilogue: add bias, store y, reduce per-channel sum / sumsq
    const size_t base = ((size_t)(b * CC + c0)) << 16;
    #pragma unroll
    for (int co = 0; co < 8; co++) {
        const float bv = bias[c0 + co];
        float s1 = 0.f, s2 = 0.f;
        #pragma unroll
        for (int rr = 0; rr < 4; rr++) {
            const int r = ty + rr * 8;
            float v = acc[rr][co] + bv;
            g_y[base + ((size_t)co << 16) + (h0 + r) * 256 + (w0 + tx)] = v;
            s1 += v;
            s2 += v * v;
        }
        #pragma unroll
        for (int o = 16; o > 0; o >>= 1) {
            s1 += __shfl_xor_sync(0xFFFFFFFFu, s1, o);
            s2 += __shfl_xor_sync(0xFFFFFFFFu, s2, o);
        }
        if (tx == 0) { s_red[ty][co][0] = s1; s_red[ty][co][1] = s2; }
    }
    __syncthreads();
    if (tid < 8) {
        float t1 = 0.f, t2 = 0.f;
        #pragma unroll
        for (int wp = 0; wp < 8; wp++) {
            t1 += s_red[wp][tid][0];
            t2 += s_red[wp][tid][1];
        }
        atomicAdd(&g_sum[c0 + tid],   (double)t1);
        atomicAdd(&g_sumsq[c0 + tid], (double)t2);
    }
}

// ---------------------------------------------------------------------------
// BN params: training-mode batch statistics (biased variance).
// ---------------------------------------------------------------------------
__global__ void bnparam_kernel(const float* __restrict__ gamma,
                               const float* __restrict__ beta) {
    int c = threadIdx.x;
    if (c < CC) {
        const double N = (double)BB * HH * WW;
        double mean = g_sum[c] / N;
        double var  = g_sumsq[c] / N - mean * mean;
        double sc   = (double)gamma[c] / sqrt(var + 1e-5);
        g_scale[c] = (float)sc;
        g_shift[c] = (float)((double)beta[c] - mean * sc);
    }
}

// ---------------------------------------------------------------------------
// Curvature: x = relu(BN(y)); out = x (.) K5  +  (x (.) D3)^2  +  x
// where (.) is CIRCULAR correlation-with-lookback: out[i,j] += f[p,q]*x[i-p,j-q].
// Block: 256 threads (32,8); tile 32x32 for one (b,c); smem 36x36 with
// top-left halo of 4 loaded with wrap, BN+ReLU applied on load.
// ---------------------------------------------------------------------------
__global__ void __launch_bounds__(256) curv_kernel(float* __restrict__ out) {
    __shared__ float s[36 * 40];
    __shared__ float k5s[25], d3s[9];

    const int tx  = threadIdx.x;
    const int ty  = threadIdx.y;
    const int tid = ty * 32 + tx;
    const int h0  = blockIdx.y * 32;
    const int w0  = blockIdx.x * 32;
    const int bc  = blockIdx.z;           // b*64 + c
    const int c   = bc & 63;

    if (tid < 25) k5s[tid] = g_K5[tid];
    if (tid < 9)  d3s[tid] = g_D3[tid];

    const float scale = g_scale[c];
    const float shift = g_shift[c];
    const float* yb = g_y + ((size_t)bc << 16);

    #pragma unroll
    for (int idx = tid; idx < 36 * 36; idx += 256) {
        int r  = idx / 36;
        int cc = idx - r * 36;
        int gh = (h0 - 4 + r) & 255;      // circular wrap
        int gw = (w0 - 4 + cc) & 255;
        float v = fmaf(yb[gh * 256 + gw], scale, shift);
        s[r * 40 + cc] = fmaxf(v, 0.f);
    }
    __syncthreads();

    #pragma unroll
    for (int rr = 0; rr < 4; rr++) {
        const int r = ty + rr * 8;
        float a = 0.f, d = 0.f;
        #pragma unroll
        for (int p = 0; p < 5; p++)
            #pragma unroll
            for (int q = 0; q < 5; q++)
                a = fmaf(k5s[p * 5 + q], s[(r + 4 - p) * 40 + (tx + 4 - q)], a);
        #pragma unroll
        for (int p = 0; p < 3; p++)
            #pragma unroll
            for (int q = 0; q < 3; q++)
                d = fmaf(d3s[p * 3 + q], s[(r + 4 - p) * 40 + (tx + 4 - q)], d);
        const float xv = s[(r + 4) * 40 + (tx + 4)];
        out[((size_t)bc << 16) + (h0 + r) * 256 + (w0 + tx)] = a + d * d + xv;
    }
}

// ---------------------------------------------------------------------------
// Launch. Inputs (metadata order): feature_map, conv_w, conv_b, bn_gamma,
// bn_beta, filt_x, filt_y. Output: float32 [8,64,256,256].
// ---------------------------------------------------------------------------
extern "C" void kernel_launch(void* const* d_in, const int* in_sizes, int n_in,
                              void* d_out, int out_size) {
    const float* feat   = (const float*)d_in[0];
    const float* conv_w = (const float*)d_in[1];
    const float* conv_b = (const float*)d_in[2];
    const float* gamma  = (const float*)d_in[3];
    const float* beta   = (const float*)d_in[4];
    const float* fx     = (const float*)d_in[5];
    const float* fy     = (const float*)d_in[6];
    float* out = (float*)d_out;

    prep_kernel<<<1, 64>>>(fx, fy);
    conv_kernel<<<dim3(8, 8, BB * 8), dim3(32, 8)>>>(feat, conv_w, conv_b);
    bnparam_kernel<<<1, 64>>>(gamma, beta);
    curv_kernel<<<dim3(8, 8, BB * CC), dim3(32, 8)>>>(out);
}

// round 7
// speedup vs baseline: 1.2629x; 1.2629x over previous
#include <cuda_runtime.h>
#include <math.h>

// ---------------------------------------------------------------------------
// Problem shape (fixed by setup_inputs): B=8, Cin=Cout=64, H=W=256
// ---------------------------------------------------------------------------
#define BB   8
#define CC   64
#define HH   256
#define WW   256
#define HW   65536           // H*W
#define NTOT 33554432        // B*C*H*W

typedef unsigned long long u64;

// Scratch: conv+bias output y (pre-BN), 128 MiB
static __device__ float  g_y[NTOT];
static __device__ double g_sum[CC], g_sumsq[CC];
static __device__ float  g_scale[CC], g_shift[CC];
static __device__ float  g_K5[25], g_D3[9];

// ---------------------------------------------------------------------------
// f32x2 packed-fp32 helpers (Blackwell FFMA2 path)
// ---------------------------------------------------------------------------
__device__ __forceinline__ u64 pk2(float lo, float hi) {
    u64 r; asm("mov.b64 %0, {%1, %2};" : "=l"(r) : "f"(lo), "f"(hi)); return r;
}
__device__ __forceinline__ void upk2(u64 v, float& lo, float& hi) {
    asm("mov.b64 {%0, %1}, %2;" : "=f"(lo), "=f"(hi) : "l"(v));
}
__device__ __forceinline__ void ffma2(u64& d, u64 a, u64 b) {
    asm("fma.rn.f32x2 %0, %1, %2, %0;" : "+l"(d) : "l"(a), "l"(b));
}
__device__ __forceinline__ u64 fmul2(u64 a, u64 b) {
    u64 r; asm("mul.rn.f32x2 %0, %1, %2;" : "=l"(r) : "l"(a), "l"(b)); return r;
}
__device__ __forceinline__ u64 fadd2(u64 a, u64 b) {
    u64 r; asm("add.rn.f32x2 %0, %1, %2;" : "=l"(r) : "l"(a), "l"(b)); return r;
}

// ---------------------------------------------------------------------------
// Prep: zero stats; build D3 = fx - fy (3x3) and K5 = fx*fx + fy*fy (5x5,
// linear self-convolution of each filter).
// ---------------------------------------------------------------------------
__global__ void prep_kernel(const float* __restrict__ fx,
                            const float* __restrict__ fy) {
    int t = threadIdx.x;
    if (t < CC) { g_sum[t] = 0.0; g_sumsq[t] = 0.0; }
    if (t < 9)  g_D3[t] = fx[t] - fy[t];
    if (t < 25) {
        int m = t / 5, n = t % 5;
        float s = 0.f;
        for (int k = 0; k < 3; k++)
            for (int l = 0; l < 3; l++) {
                int mk = m - k, nl = n - l;
                if (mk >= 0 && mk < 3 && nl >= 0 && nl < 3)
                    s += fx[k*3 + l] * fx[mk*3 + nl]
                       + fy[k*3 + l] * fy[mk*3 + nl];
            }
        g_K5[t] = s;
    }
}

// ---------------------------------------------------------------------------
// Conv 3x3 (zero pad 1) + bias via packed f32x2 FMAs, fused BN statistics.
// Block 256 (32,8). Tile: 64 wide x 32 high x 8 c_out, one batch.
// Grid (256/64=4, 256/32=8, B*8=64) = 2048 blocks.
// Thread: output cols (2tx, 2tx+1), rows ty+8*rr (rr=0..3), 8 c_out
//   -> acc[4][8] f32x2 pairs.
// smem tile layout: s_in[r][cs], cs in [4,70): gmem col = w0 + cs - 5, so the
// window pair for tap j of outputs (c,c+1) sits at smem cols (c+4+j, c+5+j);
// j=0 and j=2 pairs are 8B-aligned LDS.64, j=1 is one register pack.
// Double-buffered smem: prefetch ci+1 into registers during compute of ci.
// ---------------------------------------------------------------------------
#define SROW 72   // smem row stride in floats

__global__ void __launch_bounds__(256, 1) conv_kernel(
    const float* __restrict__ in,     // [B, 64, 256, 256]
    const float* __restrict__ wgt,    // [64, 64, 3, 3]
    const float* __restrict__ bias)   // [64]
{
    __shared__ float  s_in[2][34 * SROW];
    __shared__ float2 s_w[2][72];     // splatted (w,w) per tap, 8 c_out x 9
    __shared__ float  s_red[8][8][2];

    const int tx  = threadIdx.x;          // 0..31
    const int ty  = threadIdx.y;          // 0..7
    const int tid = ty * 32 + tx;
    const int h0  = blockIdx.y * 32;
    const int w0  = blockIdx.x * 64;
    const int b   = blockIdx.z >> 3;
    const int c0  = (blockIdx.z & 7) * 8;

    const float* inb = in + (size_t)b * (CC * HW);

    // weight element owned by this thread (tid < 72)
    const int wco = tid / 9, wk = tid - wco * 9;
    const size_t wbase = (size_t)(c0 + wco) * 576 + wk;   // + ci*9

    // ---- prologue: load tile for ci=0 directly into buffer 0 ----
    {
        #pragma unroll
        for (int it = 0; it < 5; it++) {
            int r = ty + 8 * it;
            if (r < 34) {
                int gh = h0 - 1 + r;
                #pragma unroll
                for (int j = 0; j < 3; j++) {
                    int cs = 4 + tx + 32 * j;
                    if (cs < 70) {
                        int gw = w0 + cs - 5;
                        float v = 0.f;
                        if ((unsigned)gh < 256u && (unsigned)gw < 256u)
                            v = inb[gh * 256 + gw];
                        s_in[0][r * SROW + cs] = v;
                    }
                }
            }
        }
        if (tid < 72) {
            float w = wgt[wbase];
            s_w[0][tid] = make_float2(w, w);
        }
    }
    __syncthreads();

    u64 acc[4][8];
    #pragma unroll
    for (int rr = 0; rr < 4; rr++)
        #pragma unroll
        for (int co = 0; co < 8; co++) acc[rr][co] = 0ull;  // (0.f, 0.f)

    for (int ci = 0; ci < CC; ci++) {
        const int cur = ci & 1, nxt = cur ^ 1;

        // ---- prefetch ci+1 into registers (latency hidden by compute) ----
        float pf[5][3];
        float pw = 0.f;
        if (ci < CC - 1) {
            const float* inc = inb + (size_t)(ci + 1) * HW;
            #pragma unroll
            for (int it = 0; it < 5; it++) {
                int r = ty + 8 * it;
                if (r < 34) {
                    int gh = h0 - 1 + r;
                    #pragma unroll
                    for (int j = 0; j < 3; j++) {
                        int cs = 4 + tx + 32 * j;
                        if (cs < 70) {
                            int gw = w0 + cs - 5;
                            float v = 0.f;
                            if ((unsigned)gh < 256u && (unsigned)gw < 256u)
                                v = inc[gh * 256 + gw];
                            pf[it][j] = v;
                        }
                    }
                }
            }
            if (tid < 72) pw = wgt[wbase + (size_t)(ci + 1) * 9];
        }

        // ---- gather this thread's 12 window-pair segments (f32x2) ----
        u64 a[4][9];
        const float* sb = s_in[cur];
        #pragma unroll
        for (int rr = 0; rr < 4; rr++) {
            const int orow = ty + 8 * rr;
            #pragma unroll
            for (int i = 0; i < 3; i++) {
                const float* row = sb + (orow + i) * SROW + 2 * tx;
                float2 d0 = *(const float2*)(row + 4);   // taps j=0 pair
                float2 d1 = *(const float2*)(row + 6);   // taps j=2 pair
                a[rr][3*i+0] = pk2(d0.x, d0.y);
                a[rr][3*i+1] = pk2(d0.y, d1.x);          // j=1 pair
                a[rr][3*i+2] = pk2(d1.x, d1.y);
            }
        }

        // ---- packed FMAs: 8 c_out x 4 rows x 9 taps = 288 FFMA2 ----
        const float2* wb = s_w[cur];
        #pragma unroll
        for (int co = 0; co < 8; co++) {
            u64 w[9];
            #pragma unroll
            for (int k = 0; k < 9; k++)
                w[k] = *(const u64*)&wb[co * 9 + k];     // broadcast LDS.64
            #pragma unroll
            for (int rr = 0; rr < 4; rr++)
                #pragma unroll
                for (int k = 0; k < 9; k++)
                    ffma2(acc[rr][co], a[rr][k], w[k]);
        }

        // ---- commit prefetch into the other buffer ----
        if (ci < CC - 1) {
            #pragma unroll
            for (int it = 0; it < 5; it++) {
                int r = ty + 8 * it;
                if (r < 34) {
                    #pragma unroll
                    for (int j = 0; j < 3; j++) {
                        int cs = 4 + tx + 32 * j;
                        if (cs < 70) s_in[nxt][r * SROW + cs] = pf[it][j];
                    }
                }
            }
            if (tid < 72) s_w[nxt][tid] = make_float2(pw, pw);
        }
        __syncthreads();
    }

    // ---- epilogue: bias, store y (float2), per-channel sum/sumsq ----
    const size_t obase = ((size_t)(b * CC + c0) << 16) + (size_t)(w0 + 2 * tx);
    #pragma unroll
    for (int co = 0; co < 8; co++) {
        const float bv = bias[c0 + co];
        float s1 = 0.f, s2 = 0.f;
        #pragma unroll
        for (int rr = 0; rr < 4; rr++) {
            const int orow = ty + 8 * rr;
            float v0, v1; upk2(acc[rr][co], v0, v1);
            v0 += bv; v1 += bv;
            *(float2*)&g_y[obase + ((size_t)co << 16) + (size_t)(h0 + orow) * 256]
                = make_float2(v0, v1);
            s1 += v0 + v1;
            s2 = fmaf(v0, v0, s2);
            s2 = fmaf(v1, v1, s2);
        }
        #pragma unroll
        for (int o = 16; o > 0; o >>= 1) {
            s1 += __shfl_xor_sync(0xFFFFFFFFu, s1, o);
            s2 += __shfl_xor_sync(0xFFFFFFFFu, s2, o);
        }
        if (tx == 0) { s_red[ty][co][0] = s1; s_red[ty][co][1] = s2; }
    }
    __syncthreads();
    if (tid < 8) {
        float t1 = 0.f, t2 = 0.f;
        #pragma unroll
        for (int wp = 0; wp < 8; wp++) {
            t1 += s_red[wp][tid][0];
            t2 += s_red[wp][tid][1];
        }
        atomicAdd(&g_sum[c0 + tid],   (double)t1);
        atomicAdd(&g_sumsq[c0 + tid], (double)t2);
    }
}

// ---------------------------------------------------------------------------
// BN params: training-mode batch statistics (biased variance).
// ---------------------------------------------------------------------------
__global__ void bnparam_kernel(const float* __restrict__ gamma,
                               const float* __restrict__ beta) {
    int c = threadIdx.x;
    if (c < CC) {
        const double N = (double)BB * HH * WW;
        double mean = g_sum[c] / N;
        double var  = g_sumsq[c] / N - mean * mean;
        double sc   = (double)gamma[c] / sqrt(var + 1e-5);
        g_scale[c] = (float)sc;
        g_shift[c] = (float)((double)beta[c] - mean * sc);
    }
}

// ---------------------------------------------------------------------------
// Curvature (packed f32x2): x = relu(BN(y));
// out = x (.) K5 + (x (.) D3)^2 + x  with circular wrap, (.) = lookback corr.
// Block 256 (32,8); tile 64 wide x 32 high per (b,c); grid (4, 8, 512).
// smem row m <-> gmem row (h0-4+m)&255; smem col n <-> out col n-4, so the
// tap-q pair for outputs (c, c+1) at row p is smem (c+4-q, c+5-q): three
// aligned LDS.64 per row (q=4,2,0) + two packs (q=3,1) serve K5 AND D3.
// ---------------------------------------------------------------------------
#define VROW 72

__global__ void __launch_bounds__(256) curv_kernel(float* __restrict__ out) {
    __shared__ float s[36 * VROW];
    __shared__ float s_k5[25], s_d3[9];

    const int tx  = threadIdx.x;
    const int ty  = threadIdx.y;
    const int tid = ty * 32 + tx;
    const int h0  = blockIdx.y * 32;
    const int w0  = blockIdx.x * 64;
    const int bc  = blockIdx.z;            // b*64 + c
    const int c   = bc & 63;

    if (tid < 25) s_k5[tid] = g_K5[tid];
    if (tid < 9)  s_d3[tid] = g_D3[tid];

    const float scale = g_scale[c];
    const float shift = g_shift[c];
    const float* yb = g_y + ((size_t)bc << 16);

    // cooperative tile load with wrap, BN+ReLU applied on load
    #pragma unroll
    for (int it = 0; it < 5; it++) {
        int r = ty + 8 * it;
        if (r < 36) {
            int gh = (h0 - 4 + r) & 255;
            #pragma unroll
            for (int j = 0; j < 3; j++) {
                int cc = tx + 32 * j;
                if (cc < 68) {
                    int gw = (w0 - 4 + cc) & 255;
                    float v = fmaf(yb[gh * 256 + gw], scale, shift);
                    s[r * VROW + cc] = fmaxf(v, 0.f);
                }
            }
        }
    }
    __syncthreads();

    // splat filter weights into registers (broadcast LDS, once per thread)
    u64 k5w[25], d3w[9];
    #pragma unroll
    for (int i = 0; i < 25; i++) { float w = s_k5[i]; k5w[i] = pk2(w, w); }
    #pragma unroll
    for (int i = 0; i < 9; i++)  { float w = s_d3[i]; d3w[i] = pk2(w, w); }

    const int cb = 2 * tx;                 // output col pair (cb, cb+1)
    #pragma unroll
    for (int rr = 0; rr < 4; rr++) {
        const int orow = ty + 8 * rr;
        u64 a = 0ull, d = 0ull, xc = 0ull;
        #pragma unroll
        for (int p = 0; p < 5; p++) {
            const float* row = s + (orow + 4 - p) * VROW + cb;
            float2 e0 = *(const float2*)(row);       // out cols (cb-4, cb-3)
            float2 e1 = *(const float2*)(row + 2);   // (cb-2, cb-1)
            float2 e2 = *(const float2*)(row + 4);   // (cb,   cb+1)
            u64 q4 = pk2(e0.x, e0.y);
            u64 q3 = pk2(e0.y, e1.x);
            u64 q2 = pk2(e1.x, e1.y);
            u64 q1 = pk2(e1.y, e2.x);
            u64 q0 = pk2(e2.x, e2.y);
            ffma2(a, q0, k5w[p * 5 + 0]);
            ffma2(a, q1, k5w[p * 5 + 1]);
            ffma2(a, q2, k5w[p * 5 + 2]);
            ffma2(a, q3, k5w[p * 5 + 3]);
            ffma2(a, q4, k5w[p * 5 + 4]);
            if (p < 3) {
                ffma2(d, q0, d3w[p * 3 + 0]);
                ffma2(d, q1, d3w[p * 3 + 1]);
                ffma2(d, q2, d3w[p * 3 + 2]);
            }
            if (p == 0) xc = q0;           // central x pair
        }
        u64 res = fadd2(fadd2(a, fmul2(d, d)), xc);
        float r0, r1; upk2(res, r0, r1);
        *(float2*)&out[((size_t)bc << 16) + (size_t)(h0 + orow) * 256 + w0 + cb]
            = make_float2(r0, r1);
    }
}

// ---------------------------------------------------------------------------
// Launch. Inputs (metadata order): feature_map, conv_w, conv_b, bn_gamma,
// bn_beta, filt_x, filt_y. Output: float32 [8,64,256,256].
// ---------------------------------------------------------------------------
extern "C" void kernel_launch(void* const* d_in, const int* in_sizes, int n_in,
                              void* d_out, int out_size) {
    const float* feat   = (const float*)d_in[0];
    const float* conv_w = (const float*)d_in[1];
    const float* conv_b = (const float*)d_in[2];
    const float* gamma  = (const float*)d_in[3];
    const float* beta   = (const float*)d_in[4];
    const float* fx     = (const float*)d_in[5];
    const float* fy     = (const float*)d_in[6];
    float* out = (float*)d_out;

    prep_kernel<<<1, 64>>>(fx, fy);
    conv_kernel<<<dim3(4, 8, BB * 8), dim3(32, 8)>>>(feat, conv_w, conv_b);
    bnparam_kernel<<<1, 64>>>(gamma, beta);
    curv_kernel<<<dim3(4, 8, BB * CC), dim3(32, 8)>>>(out);
}

// round 11
// speedup vs baseline: 1.4345x; 1.1359x over previous
#include <cuda_runtime.h>
#include <math.h>

// ---------------------------------------------------------------------------
// Problem shape (fixed by setup_inputs): B=8, Cin=Cout=64, H=W=256
// ---------------------------------------------------------------------------
#define BB   8
#define CC   64
#define HH   256
#define WW   256
#define HW   65536           // H*W
#define NTOT 33554432        // B*C*H*W

typedef unsigned long long u64;

// Scratch: conv+bias output y (pre-BN), 128 MiB
static __device__ float  g_y[NTOT];
static __device__ double g_sum[CC], g_sumsq[CC];
static __device__ float  g_scale[CC], g_shift[CC];
static __device__ float  g_K5[25], g_D3[9];

// ---------------------------------------------------------------------------
// f32x2 packed-fp32 helpers (Blackwell FFMA2 path)
// ---------------------------------------------------------------------------
__device__ __forceinline__ u64 pk2(float lo, float hi) {
    u64 r; asm("mov.b64 %0, {%1, %2};" : "=l"(r) : "f"(lo), "f"(hi)); return r;
}
__device__ __forceinline__ void upk2(u64 v, float& lo, float& hi) {
    asm("mov.b64 {%0, %1}, %2;" : "=f"(lo), "=f"(hi) : "l"(v));
}
__device__ __forceinline__ void ffma2(u64& d, u64 a, u64 b) {
    asm("fma.rn.f32x2 %0, %1, %2, %0;" : "+l"(d) : "l"(a), "l"(b));
}
__device__ __forceinline__ u64 fmul2(u64 a, u64 b) {
    u64 r; asm("mul.rn.f32x2 %0, %1, %2;" : "=l"(r) : "l"(a), "l"(b)); return r;
}
__device__ __forceinline__ u64 fadd2(u64 a, u64 b) {
    u64 r; asm("add.rn.f32x2 %0, %1, %2;" : "=l"(r) : "l"(a), "l"(b)); return r;
}

// ---------------------------------------------------------------------------
// Prep: zero stats; build D3 = fx - fy (3x3) and K5 = fx*fx + fy*fy (5x5,
// linear self-convolution of each filter).
// ---------------------------------------------------------------------------
__global__ void prep_kernel(const float* __restrict__ fx,
                            const float* __restrict__ fy) {
    int t = threadIdx.x;
    if (t < CC) { g_sum[t] = 0.0; g_sumsq[t] = 0.0; }
    if (t < 9)  g_D3[t] = fx[t] - fy[t];
    if (t < 25) {
        int m = t / 5, n = t % 5;
        float s = 0.f;
        for (int k = 0; k < 3; k++)
            for (int l = 0; l < 3; l++) {
                int mk = m - k, nl = n - l;
                if (mk >= 0 && mk < 3 && nl >= 0 && nl < 3)
                    s += fx[k*3 + l] * fx[mk*3 + nl]
                       + fy[k*3 + l] * fy[mk*3 + nl];
            }
        g_K5[t] = s;
    }
}

// ---------------------------------------------------------------------------
// Conv 3x3 (zero pad 1) + bias via packed f32x2 FMAs, fused BN statistics.
// Block 256 (32,8). Tile: 64 wide x 16 high x 8 c_out, one batch.
// Grid (4, 16, 64) = 4096 blocks, 2 blocks/SM.
// Thread: output cols (2tx, 2tx+1), rows ty + 8*rr (rr=0..1), 8 c_out
//   -> acc[2][8] f32x2 pairs (32 regs; no spills).
// smem tile: s_in[r][cs], cs in [4,70): gmem col = w0 + cs - 5, so the window
// pair for tap j of outputs (c,c+1) sits at smem cols (c+4+j, c+5+j); j=0 and
// j=2 pairs are aligned LDS.64, j=1 is one register pack.
// Double-buffered smem; prefetch ci+1 into registers during compute of ci.
// ---------------------------------------------------------------------------
#define SROW 72   // smem row stride in floats
#define TH   16   // tile height
#define SR   18   // tile rows incl. halo

__global__ void __launch_bounds__(256, 2) conv_kernel(
    const float* __restrict__ in,     // [B, 64, 256, 256]
    const float* __restrict__ wgt,    // [64, 64, 3, 3]
    const float* __restrict__ bias)   // [64]
{
    __shared__ float  s_in[2][SR * SROW];
    __shared__ float2 s_w[2][72];     // splatted (w,w) per tap, 8 c_out x 9
    __shared__ float  s_red[8][8][2];

    const int tx  = threadIdx.x;          // 0..31
    const int ty  = threadIdx.y;          // 0..7
    const int tid = ty * 32 + tx;
    const int h0  = blockIdx.y * TH;
    const int w0  = blockIdx.x * 64;
    const int b   = blockIdx.z >> 3;
    const int c0  = (blockIdx.z & 7) * 8;

    const float* inb = in + (size_t)b * (CC * HW);

    // weight element owned by this thread (tid < 72)
    const int wco = tid / 9, wk = tid - wco * 9;
    const size_t wbase = (size_t)(c0 + wco) * 576 + wk;   // + ci*9

    // ---- prologue: load tile for ci=0 directly into buffer 0 ----
    #pragma unroll
    for (int it = 0; it < 3; it++) {
        int r = ty + 8 * it;
        if (r < SR) {
            int gh = h0 - 1 + r;
            #pragma unroll
            for (int j = 0; j < 3; j++) {
                int cs = 4 + tx + 32 * j;
                if (cs < 70) {
                    int gw = w0 + cs - 5;
                    float v = 0.f;
                    if ((unsigned)gh < 256u && (unsigned)gw < 256u)
                        v = inb[gh * 256 + gw];
                    s_in[0][r * SROW + cs] = v;
                }
            }
        }
    }
    if (tid < 72) {
        float w = wgt[wbase];
        s_w[0][tid] = make_float2(w, w);
    }
    __syncthreads();

    u64 acc[2][8];
    #pragma unroll
    for (int rr = 0; rr < 2; rr++)
        #pragma unroll
        for (int co = 0; co < 8; co++) acc[rr][co] = 0ull;  // (0.f, 0.f)

    for (int ci = 0; ci < CC; ci++) {
        const int cur = ci & 1, nxt = cur ^ 1;

        // ---- prefetch ci+1 into registers (latency hidden by compute) ----
        float pf[3][3];
        float pw = 0.f;
        if (ci < CC - 1) {
            const float* inc = inb + (size_t)(ci + 1) * HW;
            #pragma unroll
            for (int it = 0; it < 3; it++) {
                int r = ty + 8 * it;
                if (r < SR) {
                    int gh = h0 - 1 + r;
                    #pragma unroll
                    for (int j = 0; j < 3; j++) {
                        int cs = 4 + tx + 32 * j;
                        if (cs < 70) {
                            int gw = w0 + cs - 5;
                            float v = 0.f;
                            if ((unsigned)gh < 256u && (unsigned)gw < 256u)
                                v = inc[gh * 256 + gw];
                            pf[it][j] = v;
                        }
                    }
                }
            }
            if (tid < 72) pw = wgt[wbase + (size_t)(ci + 1) * 9];
        }

        // ---- gather this thread's 6 window-pair rows (f32x2) ----
        u64 a[2][9];
        const float* sb = s_in[cur];
        #pragma unroll
        for (int rr = 0; rr < 2; rr++) {
            const int orow = ty + 8 * rr;
            #pragma unroll
            for (int i = 0; i < 3; i++) {
                const float* row = sb + (orow + i) * SROW + 2 * tx;
                float2 d0 = *(const float2*)(row + 4);   // tap j=0 pair
                float2 d1 = *(const float2*)(row + 6);   // tap j=2 pair
                a[rr][3*i+0] = pk2(d0.x, d0.y);
                a[rr][3*i+1] = pk2(d0.y, d1.x);          // j=1 pair
                a[rr][3*i+2] = pk2(d1.x, d1.y);
            }
        }

        // ---- packed FMAs: 8 c_out x 2 rows x 9 taps = 144 FFMA2 ----
        const float2* wb = s_w[cur];
        #pragma unroll
        for (int co = 0; co < 8; co++) {
            u64 w[9];
            #pragma unroll
            for (int k = 0; k < 9; k++)
                w[k] = *(const u64*)&wb[co * 9 + k];     // broadcast LDS.64
            #pragma unroll
            for (int rr = 0; rr < 2; rr++)
                #pragma unroll
                for (int k = 0; k < 9; k++)
                    ffma2(acc[rr][co], a[rr][k], w[k]);
        }

        // ---- commit prefetch into the other buffer ----
        if (ci < CC - 1) {
            #pragma unroll
            for (int it = 0; it < 3; it++) {
                int r = ty + 8 * it;
                if (r < SR) {
                    #pragma unroll
                    for (int j = 0; j < 3; j++) {
                        int cs = 4 + tx + 32 * j;
                        if (cs < 70) s_in[nxt][r * SROW + cs] = pf[it][j];
                    }
                }
            }
            if (tid < 72) s_w[nxt][tid] = make_float2(pw, pw);
        }
        __syncthreads();
    }

    // ---- epilogue: bias, store y (float2), per-channel sum/sumsq ----
    const size_t obase = ((size_t)(b * CC + c0) << 16) + (size_t)(w0 + 2 * tx);
    #pragma unroll
    for (int co = 0; co < 8; co++) {
        const float bv = bias[c0 + co];
        float s1 = 0.f, s2 = 0.f;
        #pragma unroll
        for (int rr = 0; rr < 2; rr++) {
            const int orow = ty + 8 * rr;
            float v0, v1; upk2(acc[rr][co], v0, v1);
            v0 += bv; v1 += bv;
            *(float2*)&g_y[obase + ((size_t)co << 16) + (size_t)(h0 + orow) * 256]
                = make_float2(v0, v1);
            s1 += v0 + v1;
            s2 = fmaf(v0, v0, s2);
            s2 = fmaf(v1, v1, s2);
        }
        #pragma unroll
        for (int o = 16; o > 0; o >>= 1) {
            s1 += __shfl_xor_sync(0xFFFFFFFFu, s1, o);
            s2 += __shfl_xor_sync(0xFFFFFFFFu, s2, o);
        }
        if (tx == 0) { s_red[ty][co][0] = s1; s_red[ty][co][1] = s2; }
    }
    __syncthreads();
    if (tid < 8) {
        float t1 = 0.f, t2 = 0.f;
        #pragma unroll
        for (int wp = 0; wp < 8; wp++) {
            t1 += s_red[wp][tid][0];
            t2 += s_red[wp][tid][1];
        }
        atomicAdd(&g_sum[c0 + tid],   (double)t1);
        atomicAdd(&g_sumsq[c0 + tid], (double)t2);
    }
}

// ---------------------------------------------------------------------------
// BN params: training-mode batch statistics (biased variance).
// ---------------------------------------------------------------------------
__global__ void bnparam_kernel(const float* __restrict__ gamma,
                               const float* __restrict__ beta) {
    int c = threadIdx.x;
    if (c < CC) {
        const double N = (double)BB * HH * WW;
        double mean = g_sum[c] / N;
        double var  = g_sumsq[c] / N - mean * mean;
        double sc   = (double)gamma[c] / sqrt(var + 1e-5);
        g_scale[c] = (float)sc;
        g_shift[c] = (float)((double)beta[c] - mean * sc);
    }
}

// ---------------------------------------------------------------------------
// Curvature (packed f32x2): x = relu(BN(y));
// out = x (.) K5 + (x (.) D3)^2 + x  with circular wrap, (.) = lookback corr.
// Block 256 (32,8); tile 64 wide x 32 high per (b,c); grid (4, 8, 512).
// ---------------------------------------------------------------------------
#define VROW 72

__global__ void __launch_bounds__(256) curv_kernel(float* __restrict__ out) {
    __shared__ float s[36 * VROW];
    __shared__ float s_k5[25], s_d3[9];

    const int tx  = threadIdx.x;
    const int ty  = threadIdx.y;
    const int tid = ty * 32 + tx;
    const int h0  = blockIdx.y * 32;
    const int w0  = blockIdx.x * 64;
    const int bc  = blockIdx.z;            // b*64 + c
    const int c   = bc & 63;

    if (tid < 25) s_k5[tid] = g_K5[tid];
    if (tid < 9)  s_d3[tid] = g_D3[tid];

    const float scale = g_scale[c];
    const float shift = g_shift[c];
    const float* yb = g_y + ((size_t)bc << 16);

    // cooperative tile load with wrap, BN+ReLU applied on load
    #pragma unroll
    for (int it = 0; it < 5; it++) {
        int r = ty + 8 * it;
        if (r < 36) {
            int gh = (h0 - 4 + r) & 255;
            #pragma unroll
            for (int j = 0; j < 3; j++) {
                int cc = tx + 32 * j;
                if (cc < 68) {
                    int gw = (w0 - 4 + cc) & 255;
                    float v = fmaf(yb[gh * 256 + gw], scale, shift);
                    s[r * VROW + cc] = fmaxf(v, 0.f);
                }
            }
        }
    }
    __syncthreads();

    // splat filter weights into registers (broadcast LDS, once per thread)
    u64 k5w[25], d3w[9];
    #pragma unroll
    for (int i = 0; i < 25; i++) { float w = s_k5[i]; k5w[i] = pk2(w, w); }
    #pragma unroll
    for (int i = 0; i < 9; i++)  { float w = s_d3[i]; d3w[i] = pk2(w, w); }

    const int cb = 2 * tx;                 // output col pair (cb, cb+1)
    #pragma unroll
    for (int rr = 0; rr < 4; rr++) {
        const int orow = ty + 8 * rr;
        u64 a = 0ull, d = 0ull, xc = 0ull;
        #pragma unroll
        for (int p = 0; p < 5; p++) {
            const float* row = s + (orow + 4 - p) * VROW + cb;
            float2 e0 = *(const float2*)(row);       // out cols (cb-4, cb-3)
            float2 e1 = *(const float2*)(row + 2);   // (cb-2, cb-1)
            float2 e2 = *(const float2*)(row + 4);   // (cb,   cb+1)
            u64 q4 = pk2(e0.x, e0.y);
            u64 q3 = pk2(e0.y, e1.x);
            u64 q2 = pk2(e1.x, e1.y);
            u64 q1 = pk2(e1.y, e2.x);
            u64 q0 = pk2(e2.x, e2.y);
            ffma2(a, q0, k5w[p * 5 + 0]);
            ffma2(a, q1, k5w[p * 5 + 1]);
            ffma2(a, q2, k5w[p * 5 + 2]);
            ffma2(a, q3, k5w[p * 5 + 3]);
            ffma2(a, q4, k5w[p * 5 + 4]);
            if (p < 3) {
                ffma2(d, q0, d3w[p * 3 + 0]);
                ffma2(d, q1, d3w[p * 3 + 1]);
                ffma2(d, q2, d3w[p * 3 + 2]);
            }
            if (p == 0) xc = q0;           // central x pair
        }
        u64 res = fadd2(fadd2(a, fmul2(d, d)), xc);
        float r0, r1; upk2(res, r0, r1);
        *(float2*)&out[((size_t)bc << 16) + (size_t)(h0 + orow) * 256 + w0 + cb]
            = make_float2(r0, r1);
    }
}

// ---------------------------------------------------------------------------
// Launch. Inputs (metadata order): feature_map, conv_w, conv_b, bn_gamma,
// bn_beta, filt_x, filt_y. Output: float32 [8,64,256,256].
// ---------------------------------------------------------------------------
extern "C" void kernel_launch(void* const* d_in, const int* in_sizes, int n_in,
                              void* d_out, int out_size) {
    const float* feat   = (const float*)d_in[0];
    const float* conv_w = (const float*)d_in[1];
    const float* conv_b = (const float*)d_in[2];
    const float* gamma  = (const float*)d_in[3];
    const float* beta   = (const float*)d_in[4];
    const float* fx     = (const float*)d_in[5];
    const float* fy     = (const float*)d_in[6];
    float* out = (float*)d_out;

    prep_kernel<<<1, 64>>>(fx, fy);
    conv_kernel<<<dim3(4, 16, BB * 8), dim3(32, 8)>>>(feat, conv_w, conv_b);
    bnparam_kernel<<<1, 64>>>(gamma, beta);
    curv_kernel<<<dim3(4, 8, BB * CC), dim3(32, 8)>>>(out);
}

// round 16
// speedup vs baseline: 3.1789x; 2.2160x over previous
#include <cuda_runtime.h>
#include <cuda_bf16.h>
#include <math.h>
#include <stdint.h>

// ---------------------------------------------------------------------------
// Problem shape (fixed by setup_inputs): B=8, Cin=Cout=64, H=W=256
// ---------------------------------------------------------------------------
#define BB   8
#define CC   64
#define HH   256
#define WW   256
#define HW   65536           // H*W
#define NTOT 33554432        // B*C*H*W

// Scratch
static __device__ float          g_y[NTOT];                 // conv+bias output
static __device__ __nv_bfloat16  g_xhi[NTOT], g_xlo[NTOT];  // NHWC split input
static __device__ __nv_bfloat16  g_whi[3*64*192], g_wlo[3*64*192]; // per-dy W
static __device__ double g_sum[CC], g_sumsq[CC];
static __device__ float  g_scale[CC], g_shift[CC];
static __device__ float  g_K5[25], g_D3[9];

typedef unsigned long long u64;

// ---------------------------------------------------------------------------
// f32x2 helpers (used by curv kernel)
// ---------------------------------------------------------------------------
__device__ __forceinline__ u64 pk2(float lo, float hi) {
    u64 r; asm("mov.b64 %0, {%1, %2};" : "=l"(r) : "f"(lo), "f"(hi)); return r;
}
__device__ __forceinline__ void upk2(u64 v, float& lo, float& hi) {
    asm("mov.b64 {%0, %1}, %2;" : "=f"(lo), "=f"(hi) : "l"(v));
}
__device__ __forceinline__ void ffma2(u64& d, u64 a, u64 b) {
    asm("fma.rn.f32x2 %0, %1, %2, %0;" : "+l"(d) : "l"(a), "l"(b));
}
__device__ __forceinline__ u64 fmul2(u64 a, u64 b) {
    u64 r; asm("mul.rn.f32x2 %0, %1, %2;" : "=l"(r) : "l"(a), "l"(b)); return r;
}
__device__ __forceinline__ u64 fadd2(u64 a, u64 b) {
    u64 r; asm("add.rn.f32x2 %0, %1, %2;" : "=l"(r) : "l"(a), "l"(b)); return r;
}

// ---------------------------------------------------------------------------
// Warp-level bf16 MMA (sm_80+ PTX; compiles for compute_103).
// D(16x8,f32) += A(16x16,bf16,row) x B(16x8,bf16,col)
// ---------------------------------------------------------------------------
__device__ __forceinline__ void mma16816(float* c,
                                         uint32_t a0, uint32_t a1,
                                         uint32_t a2, uint32_t a3,
                                         uint32_t b0, uint32_t b1) {
    asm volatile(
        "mma.sync.aligned.m16n8k16.row.col.f32.bf16.bf16.f32 "
        "{%0,%1,%2,%3}, {%4,%5,%6,%7}, {%8,%9}, {%0,%1,%2,%3};"
        : "+f"(c[0]), "+f"(c[1]), "+f"(c[2]), "+f"(c[3])
        : "r"(a0), "r"(a1), "r"(a2), "r"(a3), "r"(b0), "r"(b1));
}

// ---------------------------------------------------------------------------
// Prep: zero stats; build D3 = fx - fy (3x3) and K5 = fx*fx + fy*fy (5x5).
// ---------------------------------------------------------------------------
__global__ void prep_kernel(const float* __restrict__ fx,
                            const float* __restrict__ fy) {
    int t = threadIdx.x;
    if (t < CC) { g_sum[t] = 0.0; g_sumsq[t] = 0.0; }
    if (t < 9)  g_D3[t] = fx[t] - fy[t];
    if (t < 25) {
        int m = t / 5, n = t % 5;
        float s = 0.f;
        for (int k = 0; k < 3; k++)
            for (int l = 0; l < 3; l++) {
                int mk = m - k, nl = n - l;
                if (mk >= 0 && mk < 3 && nl >= 0 && nl < 3)
                    s += fx[k*3 + l] * fx[mk*3 + nl]
                       + fy[k*3 + l] * fy[mk*3 + nl];
            }
        g_K5[t] = s;
    }
}

// ---------------------------------------------------------------------------
// Split weights: W[co][ci][dy][dx] -> Whi/Wlo[dy][co][dx*64+ci] bf16 pair.
// ---------------------------------------------------------------------------
__global__ void wsplit_kernel(const float* __restrict__ wgt) {
    int t = blockIdx.x * 256 + threadIdx.x;      // < 3*64*192
    int dy  = t / 12288;
    int rem = t - dy * 12288;
    int co  = rem / 192;
    int k   = rem - co * 192;
    int dx  = k >> 6, ci = k & 63;
    float w = wgt[((co * 64 + ci) * 3 + dy) * 3 + dx];
    __nv_bfloat16 hi = __float2bfloat16(w);
    __nv_bfloat16 lo = __float2bfloat16(w - __bfloat162float(hi));
    g_whi[t] = hi;
    g_wlo[t] = lo;
}

// ---------------------------------------------------------------------------
// Split + transpose input: x[b][ci][h][w] f32 -> Xhi/Xlo[b][h][w][ci] bf16.
// grid 2048 (= b*256 + h), block 256; smem tile 64ci x 32w.
// ---------------------------------------------------------------------------
__global__ void xsplit_kernel(const float* __restrict__ in) {
    __shared__ float s[64][33];
    const int bh = blockIdx.x;
    const int b = bh >> 8, h = bh & 255;
    const int tid = threadIdx.x;

    for (int wc = 0; wc < 8; wc++) {
        const int w0 = wc * 32;
        // phase 1: coalesced read along w
        #pragma unroll
        for (int it = 0; it < 8; it++) {
            int ci = (tid >> 5) + it * 8;
            int w  = tid & 31;
            s[ci][w] = in[(((size_t)b * 64 + ci) << 16) + h * 256 + w0 + w];
        }
        __syncthreads();
        // phase 2: coalesced write along ci — 8 iters so w covers 0..31
        #pragma unroll
        for (int it = 0; it < 8; it++) {
            int w  = (tid >> 6) + it * 4;
            int ci = tid & 63;
            float v = s[ci][w];
            __nv_bfloat16 hi = __float2bfloat16(v);
            __nv_bfloat16 lo = __float2bfloat16(v - __bfloat162float(hi));
            size_t o = (((size_t)bh) * 256 + w0 + w) * 64 + ci;
            g_xhi[o] = hi;
            g_xlo[o] = lo;
        }
        __syncthreads();
    }
}

// ---------------------------------------------------------------------------
// Conv via mma.sync bf16 implicit GEMM, 2-term bf16 split (3 GEMM combos).
// CTA = (b, h, 64-wide w-strip); block 128 (4 warps), each warp owns m16 x n64.
// Per dy strip: stage A[64 x 192] (hi/lo) and B[64 x 192] (hi/lo) in smem
// (K = dx*64 + ci), then accumulate 3 combos x 12 K-steps in fp32 registers.
// smem rows padded to 200 bf16 (400 B) -> conflict-free fragment loads.
// ---------------------------------------------------------------------------
#define ASTRIDE 200           // bf16 elements per smem row
#define A_HI_B  0
#define A_LO_B  25600
#define B_HI_B  51200
#define B_LO_B  76800
#define CONV_SMEM 102400

__global__ void __launch_bounds__(128) conv_mma_kernel(
    const float* __restrict__ bias)
{
    extern __shared__ char smem[];
    __nv_bfloat16* const A_hi = (__nv_bfloat16*)(smem + A_HI_B);
    __nv_bfloat16* const A_lo = (__nv_bfloat16*)(smem + A_LO_B);
    __nv_bfloat16* const B_hi = (__nv_bfloat16*)(smem + B_HI_B);
    __nv_bfloat16* const B_lo = (__nv_bfloat16*)(smem + B_LO_B);

    const int tid  = threadIdx.x;
    const int wid  = tid >> 5;
    const int lane = tid & 31;
    const int gid  = lane >> 2;       // 0..7
    const int tig  = lane & 3;        // 0..3

    const int t  = blockIdx.x;        // 0..8191
    const int b  = t >> 10;
    const int h  = (t >> 2) & 255;
    const int w0 = (t & 3) * 64;

    float acc[8][4];
    #pragma unroll
    for (int nt = 0; nt < 8; nt++)
        #pragma unroll
        for (int i = 0; i < 4; i++) acc[nt][i] = 0.f;

    for (int dy = 0; dy < 3; dy++) {
        const int gh = h - 1 + dy;
        const bool ghok = ((unsigned)gh < 256u);
        const size_t rowbase = ((size_t)(b * 256 + gh)) * 256;

        // ---- stage A_hi/A_lo: 1536 16B-chunks each (64 rows x 24 chunks) ----
        #pragma unroll
        for (int sp = 0; sp < 2; sp++) {
            const __nv_bfloat16* src = sp ? g_xlo : g_xhi;
            char* dst = smem + (sp ? A_LO_B : A_HI_B);
            #pragma unroll
            for (int it = 0; it < 12; it++) {
                int idx = it * 128 + tid;
                int r   = idx / 24;           // w_local 0..63
                int k16 = idx - r * 24;       // 16B chunk (dx*8 + ci8)
                int dx  = k16 >> 3;
                int gw  = w0 + r - 1 + dx;
                uint4 v = make_uint4(0u, 0u, 0u, 0u);
                if (ghok && (unsigned)gw < 256u)
                    v = *(const uint4*)(src + (rowbase + gw) * 64 + (k16 & 7) * 8);
                *(uint4*)(dst + r * 400 + k16 * 16) = v;
            }
        }
        // ---- stage B_hi/B_lo: 1536 16B-chunks each (64 co x 24 chunks) ----
        #pragma unroll
        for (int sp = 0; sp < 2; sp++) {
            const __nv_bfloat16* src = (sp ? g_wlo : g_whi) + dy * 12288;
            char* dst = smem + (sp ? B_LO_B : B_HI_B);
            #pragma unroll
            for (int it = 0; it < 12; it++) {
                int idx = it * 128 + tid;
                int co  = idx / 24;
                int k16 = idx - co * 24;
                uint4 v = *(const uint4*)(src + co * 192 + k16 * 8);
                *(uint4*)(dst + co * 400 + k16 * 16) = v;
            }
        }
        __syncthreads();

        // ---- 3 combos x 12 K-steps x 8 n-tiles of m16n8k16 ----
        const __nv_bfloat16* const Asel[3] = { A_hi, A_lo, A_hi };
        const __nv_bfloat16* const Bsel[3] = { B_hi, B_hi, B_lo };
        #pragma unroll
        for (int cmb = 0; cmb < 3; cmb++) {
            const __nv_bfloat16* Ab = Asel[cmb] + (wid * 16 + gid) * ASTRIDE + tig * 2;
            const __nv_bfloat16* Bb = Bsel[cmb] + gid * ASTRIDE + tig * 2;
            #pragma unroll
            for (int ks = 0; ks < 12; ks++) {
                const __nv_bfloat16* ap = Ab + ks * 16;
                uint32_t a0 = *(const uint32_t*)(ap);
                uint32_t a1 = *(const uint32_t*)(ap + 8 * ASTRIDE);
                uint32_t a2 = *(const uint32_t*)(ap + 8);
                uint32_t a3 = *(const uint32_t*)(ap + 8 * ASTRIDE + 8);
                const __nv_bfloat16* bp = Bb + ks * 16;
                #pragma unroll
                for (int nt = 0; nt < 8; nt++) {
                    uint32_t b0 = *(const uint32_t*)(bp + nt * 8 * ASTRIDE);
                    uint32_t b1 = *(const uint32_t*)(bp + nt * 8 * ASTRIDE + 8);
                    mma16816(acc[nt], a0, a1, a2, a3, b0, b1);
                }
            }
        }
        __syncthreads();
    }

    // ---- epilogue: add bias, store y (NCHW) ----
    // Thread owns D rows m0 = wid*16+gid and m0+8; cols co = nt*8 + 2*tig (+1).
    const size_t obase = (((size_t)b * 64) << 16) + (size_t)h * 256 + (size_t)w0;
    const int m0 = wid * 16 + gid;
    #pragma unroll
    for (int nt = 0; nt < 8; nt++) {
        const int co0 = nt * 8 + tig * 2;
        const float bv0 = __ldg(&bias[co0]);
        const float bv1 = __ldg(&bias[co0 + 1]);
        g_y[obase + ((size_t)co0       << 16) + m0]     = acc[nt][0] + bv0;
        g_y[obase + ((size_t)(co0 + 1) << 16) + m0]     = acc[nt][1] + bv1;
        g_y[obase + ((size_t)co0       << 16) + m0 + 8] = acc[nt][2] + bv0;
        g_y[obase + ((size_t)(co0 + 1) << 16) + m0 + 8] = acc[nt][3] + bv1;
    }
}

// ---------------------------------------------------------------------------
// BN statistics over g_y: grid 1024 = 64 co x 16 slabs, block 256.
// ---------------------------------------------------------------------------
__global__ void stats_kernel() {
    __shared__ float sred[8][2];
    const int co   = blockIdx.x & 63;
    const int slab = blockIdx.x >> 6;
    const int tid  = threadIdx.x;

    float s1 = 0.f, s2 = 0.f;
    const int j0 = slab * 32768;
    for (int it = 0; it < 32; it++) {
        int j = j0 + (it * 256 + tid) * 4;
        int bb = j >> 16, pix = j & 65535;
        float4 v = *(const float4*)&g_y[(((size_t)bb * 64 + co) << 16) + pix];
        s1 += v.x + v.y + v.z + v.w;
        s2 = fmaf(v.x, v.x, s2); s2 = fmaf(v.y, v.y, s2);
        s2 = fmaf(v.z, v.z, s2); s2 = fmaf(v.w, v.w, s2);
    }
    #pragma unroll
    for (int o = 16; o > 0; o >>= 1) {
        s1 += __shfl_xor_sync(0xFFFFFFFFu, s1, o);
        s2 += __shfl_xor_sync(0xFFFFFFFFu, s2, o);
    }
    if ((tid & 31) == 0) { sred[tid >> 5][0] = s1; sred[tid >> 5][1] = s2; }
    __syncthreads();
    if (tid == 0) {
        float t1 = 0.f, t2 = 0.f;
        #pragma unroll
        for (int w = 0; w < 8; w++) { t1 += sred[w][0]; t2 += sred[w][1]; }
        atomicAdd(&g_sum[co],   (double)t1);
        atomicAdd(&g_sumsq[co], (double)t2);
    }
}

// ---------------------------------------------------------------------------
// BN params: training-mode batch statistics (biased variance).
// ---------------------------------------------------------------------------
__global__ void bnparam_kernel(const float* __restrict__ gamma,
                               const float* __restrict__ beta) {
    int c = threadIdx.x;
    if (c < CC) {
        const double N = (double)BB * HH * WW;
        double mean = g_sum[c] / N;
        double var  = g_sumsq[c] / N - mean * mean;
        double sc   = (double)gamma[c] / sqrt(var + 1e-5);
        g_scale[c] = (float)sc;
        g_shift[c] = (float)((double)beta[c] - mean * sc);
    }
}

// ---------------------------------------------------------------------------
// Curvature (packed f32x2): x = relu(BN(y));
// out = x (.) K5 + (x (.) D3)^2 + x  with circular wrap (lookback corr).
// ---------------------------------------------------------------------------
#define VROW 72

__global__ void __launch_bounds__(256) curv_kernel(float* __restrict__ out) {
    __shared__ float s[36 * VROW];
    __shared__ float s_k5[25], s_d3[9];

    const int tx  = threadIdx.x;
    const int ty  = threadIdx.y;
    const int tid = ty * 32 + tx;
    const int h0  = blockIdx.y * 32;
    const int w0  = blockIdx.x * 64;
    const int bc  = blockIdx.z;            // b*64 + c
    const int c   = bc & 63;

    if (tid < 25) s_k5[tid] = g_K5[tid];
    if (tid < 9)  s_d3[tid] = g_D3[tid];

    const float scale = g_scale[c];
    const float shift = g_shift[c];
    const float* yb = g_y + ((size_t)bc << 16);

    #pragma unroll
    for (int it = 0; it < 5; it++) {
        int r = ty + 8 * it;
        if (r < 36) {
            int gh = (h0 - 4 + r) & 255;
            #pragma unroll
            for (int j = 0; j < 3; j++) {
                int cc = tx + 32 * j;
                if (cc < 68) {
                    int gw = (w0 - 4 + cc) & 255;
                    float v = fmaf(yb[gh * 256 + gw], scale, shift);
                    s[r * VROW + cc] = fmaxf(v, 0.f);
                }
            }
        }
    }
    __syncthreads();

    u64 k5w[25], d3w[9];
    #pragma unroll
    for (int i = 0; i < 25; i++) { float w = s_k5[i]; k5w[i] = pk2(w, w); }
    #pragma unroll
    for (int i = 0; i < 9; i++)  { float w = s_d3[i]; d3w[i] = pk2(w, w); }

    const int cb = 2 * tx;
    #pragma unroll
    for (int rr = 0; rr < 4; rr++) {
        const int orow = ty + 8 * rr;
        u64 a = 0ull, d = 0ull, xc = 0ull;
        #pragma unroll
        for (int p = 0; p < 5; p++) {
            const float* row = s + (orow + 4 - p) * VROW + cb;
            float2 e0 = *(const float2*)(row);
            float2 e1 = *(const float2*)(row + 2);
            float2 e2 = *(const float2*)(row + 4);
            u64 q4 = pk2(e0.x, e0.y);
            u64 q3 = pk2(e0.y, e1.x);
            u64 q2 = pk2(e1.x, e1.y);
            u64 q1 = pk2(e1.y, e2.x);
            u64 q0 = pk2(e2.x, e2.y);
            ffma2(a, q0, k5w[p * 5 + 0]);
            ffma2(a, q1, k5w[p * 5 + 1]);
            ffma2(a, q2, k5w[p * 5 + 2]);
            ffma2(a, q3, k5w[p * 5 + 3]);
            ffma2(a, q4, k5w[p * 5 + 4]);
            if (p < 3) {
                ffma2(d, q0, d3w[p * 3 + 0]);
                ffma2(d, q1, d3w[p * 3 + 1]);
                ffma2(d, q2, d3w[p * 3 + 2]);
            }
            if (p == 0) xc = q0;
        }
        u64 res = fadd2(fadd2(a, fmul2(d, d)), xc);
        float r0, r1; upk2(res, r0, r1);
        *(float2*)&out[((size_t)bc << 16) + (size_t)(h0 + orow) * 256 + w0 + cb]
            = make_float2(r0, r1);
    }
}

// ---------------------------------------------------------------------------
// Launch. Inputs: feature_map, conv_w, conv_b, bn_gamma, bn_beta, filt_x,
// filt_y. Output: float32 [8,64,256,256].
// ---------------------------------------------------------------------------
extern "C" void kernel_launch(void* const* d_in, const int* in_sizes, int n_in,
                              void* d_out, int out_size) {
    const float* feat   = (const float*)d_in[0];
    const float* conv_w = (const float*)d_in[1];
    const float* conv_b = (const float*)d_in[2];
    const float* gamma  = (const float*)d_in[3];
    const float* beta   = (const float*)d_in[4];
    const float* fx     = (const float*)d_in[5];
    const float* fy     = (const float*)d_in[6];
    float* out = (float*)d_out;

    cudaFuncSetAttribute(conv_mma_kernel,
                         cudaFuncAttributeMaxDynamicSharedMemorySize, CONV_SMEM);

    prep_kernel<<<1, 64>>>(fx, fy);
    wsplit_kernel<<<144, 256>>>(conv_w);
    xsplit_kernel<<<2048, 256>>>(feat);
    conv_mma_kernel<<<8192, 128, CONV_SMEM>>>(conv_b);
    stats_kernel<<<1024, 256>>>();
    bnparam_kernel<<<1, 64>>>(gamma, beta);
    curv_kernel<<<dim3(4, 8, BB * CC), dim3(32, 8)>>>(out);
}

// round 17
// speedup vs baseline: 3.8038x; 1.1966x over previous
#include <cuda_runtime.h>
#include <cuda_bf16.h>
#include <math.h>
#include <stdint.h>

// ---------------------------------------------------------------------------
// Problem shape (fixed by setup_inputs): B=8, Cin=Cout=64, H=W=256
// ---------------------------------------------------------------------------
#define BB   8
#define CC   64
#define HH   256
#define WW   256
#define HW   65536           // H*W
#define NTOT 33554432        // B*C*H*W

// Scratch
static __device__ float          g_y[NTOT];                 // conv+bias output
static __device__ __nv_bfloat16  g_xhi[NTOT], g_xlo[NTOT];  // NHWC split input
static __device__ __nv_bfloat16  g_whi[3*64*192], g_wlo[3*64*192]; // per-dy W
static __device__ double g_sum[CC], g_sumsq[CC];
static __device__ float  g_scale[CC], g_shift[CC];
static __device__ float  g_K5[25], g_D3[9];

typedef unsigned long long u64;

// ---------------------------------------------------------------------------
// f32x2 helpers (used by curv kernel)
// ---------------------------------------------------------------------------
__device__ __forceinline__ u64 pk2(float lo, float hi) {
    u64 r; asm("mov.b64 %0, {%1, %2};" : "=l"(r) : "f"(lo), "f"(hi)); return r;
}
__device__ __forceinline__ void upk2(u64 v, float& lo, float& hi) {
    asm("mov.b64 {%0, %1}, %2;" : "=f"(lo), "=f"(hi) : "l"(v));
}
__device__ __forceinline__ void ffma2(u64& d, u64 a, u64 b) {
    asm("fma.rn.f32x2 %0, %1, %2, %0;" : "+l"(d) : "l"(a), "l"(b));
}
__device__ __forceinline__ u64 fmul2(u64 a, u64 b) {
    u64 r; asm("mul.rn.f32x2 %0, %1, %2;" : "=l"(r) : "l"(a), "l"(b)); return r;
}
__device__ __forceinline__ u64 fadd2(u64 a, u64 b) {
    u64 r; asm("add.rn.f32x2 %0, %1, %2;" : "=l"(r) : "l"(a), "l"(b)); return r;
}

// ---------------------------------------------------------------------------
// Tensor-core helpers (arch-neutral PTX, compiles for compute_103)
// ---------------------------------------------------------------------------
__device__ __forceinline__ void mma16816(float* c,
                                         uint32_t a0, uint32_t a1,
                                         uint32_t a2, uint32_t a3,
                                         uint32_t b0, uint32_t b1) {
    asm volatile(
        "mma.sync.aligned.m16n8k16.row.col.f32.bf16.bf16.f32 "
        "{%0,%1,%2,%3}, {%4,%5,%6,%7}, {%8,%9}, {%0,%1,%2,%3};"
        : "+f"(c[0]), "+f"(c[1]), "+f"(c[2]), "+f"(c[3])
        : "r"(a0), "r"(a1), "r"(a2), "r"(a3), "r"(b0), "r"(b1));
}

#define LDM4(r, addr) \
    asm volatile("ldmatrix.sync.aligned.m8n8.x4.shared.b16 {%0,%1,%2,%3}, [%4];" \
        : "=r"((r)[0]), "=r"((r)[1]), "=r"((r)[2]), "=r"((r)[3]) \
        : "r"(addr))

__device__ __forceinline__ uint32_t smem_u32(const void* p) {
    uint32_t a;
    asm("{ .reg .u64 t; cvta.to.shared.u64 t, %1; cvt.u32.u64 %0, t; }"
        : "=r"(a) : "l"(p));
    return a;
}

// ---------------------------------------------------------------------------
// Prep: zero stats; build D3 = fx - fy (3x3) and K5 = fx*fx + fy*fy (5x5).
// ---------------------------------------------------------------------------
__global__ void prep_kernel(const float* __restrict__ fx,
                            const float* __restrict__ fy) {
    int t = threadIdx.x;
    if (t < CC) { g_sum[t] = 0.0; g_sumsq[t] = 0.0; }
    if (t < 9)  g_D3[t] = fx[t] - fy[t];
    if (t < 25) {
        int m = t / 5, n = t % 5;
        float s = 0.f;
        for (int k = 0; k < 3; k++)
            for (int l = 0; l < 3; l++) {
                int mk = m - k, nl = n - l;
                if (mk >= 0 && mk < 3 && nl >= 0 && nl < 3)
                    s += fx[k*3 + l] * fx[mk*3 + nl]
                       + fy[k*3 + l] * fy[mk*3 + nl];
            }
        g_K5[t] = s;
    }
}

// ---------------------------------------------------------------------------
// Split weights: W[co][ci][dy][dx] -> Whi/Wlo[dy][co][dx*64+ci] bf16 pair.
// ---------------------------------------------------------------------------
__global__ void wsplit_kernel(const float* __restrict__ wgt) {
    int t = blockIdx.x * 256 + threadIdx.x;      // < 3*64*192
    int dy  = t / 12288;
    int rem = t - dy * 12288;
    int co  = rem / 192;
    int k   = rem - co * 192;
    int dx  = k >> 6, ci = k & 63;
    float w = wgt[((co * 64 + ci) * 3 + dy) * 3 + dx];
    __nv_bfloat16 hi = __float2bfloat16(w);
    __nv_bfloat16 lo = __float2bfloat16(w - __bfloat162float(hi));
    g_whi[t] = hi;
    g_wlo[t] = lo;
}

// ---------------------------------------------------------------------------
// Split + transpose input: x[b][ci][h][w] f32 -> Xhi/Xlo[b][h][w][ci] bf16.
// grid 2048 (= b*256 + h), block 256; smem tile 64ci x 32w.
// ---------------------------------------------------------------------------
__global__ void xsplit_kernel(const float* __restrict__ in) {
    __shared__ float s[64][33];
    const int bh = blockIdx.x;
    const int b = bh >> 8, h = bh & 255;
    const int tid = threadIdx.x;

    for (int wc = 0; wc < 8; wc++) {
        const int w0 = wc * 32;
        #pragma unroll
        for (int it = 0; it < 8; it++) {
            int ci = (tid >> 5) + it * 8;
            int w  = tid & 31;
            s[ci][w] = in[(((size_t)b * 64 + ci) << 16) + h * 256 + w0 + w];
        }
        __syncthreads();
        #pragma unroll
        for (int it = 0; it < 8; it++) {
            int w  = (tid >> 6) + it * 4;
            int ci = tid & 63;
            float v = s[ci][w];
            __nv_bfloat16 hi = __float2bfloat16(v);
            __nv_bfloat16 lo = __float2bfloat16(v - __bfloat162float(hi));
            size_t o = (((size_t)bh) * 256 + w0 + w) * 64 + ci;
            g_xhi[o] = hi;
            g_xlo[o] = lo;
        }
        __syncthreads();
    }
}

// ---------------------------------------------------------------------------
// Conv via mma.sync bf16 implicit GEMM, 2-term bf16 split, ldmatrix loads.
// CTA = (b, h, 128-wide w-half); block 128 (4 warps), warp tile m32 x n64.
// A smem: [130 w-rows][64 ci] (halo rows w0-1 .. w0+128), row stride 144 B,
//   hi and lo planes. dx is handled by A-row offset; K per dx = 64 (4 ksteps).
// B smem: [64 co][192 = dx*64+ci], row stride 400 B, hi and lo planes.
// Per (dx,ks): 12 ldmatrix.x4 feed 48 HMMA (3 split-combos).
// ---------------------------------------------------------------------------
#define A_HI_B  0
#define A_LO_B  18720        // 130*144
#define B_HI_B  37440
#define B_LO_B  63040        // +64*400
#define CONV_SMEM 88640

__global__ void __launch_bounds__(128, 2) conv_mma_kernel(
    const float* __restrict__ bias)
{
    extern __shared__ char smem[];
    const uint32_t sb = smem_u32(smem);

    const int tid  = threadIdx.x;
    const int wid  = tid >> 5;
    const int lane = tid & 31;
    const int gid  = lane >> 2;       // 0..7
    const int tig  = lane & 3;        // 0..3
    const int t8   = lane >> 3;       // ldmatrix tile id 0..3

    const int t    = blockIdx.x;      // 0..4095
    const int b    = t >> 9;
    const int h    = (t >> 1) & 255;
    const int w0   = (t & 1) * 128;

    // per-lane ldmatrix address components
    const int arow  = (t8 & 1) * 8 + (lane & 7);   // + wid*32 + mt*16 + dx
    const int acolb = (t8 >> 1) * 16;              // byte offset in k
    const int brow  = (t8 >> 1) * 8 + (lane & 7);  // + p*16
    const int bkb   = (t8 & 1) * 16;

    const uint32_t raBaseH = sb + A_HI_B + (wid * 32 + arow) * 144 + acolb;
    const uint32_t raBaseL = sb + A_LO_B + (wid * 32 + arow) * 144 + acolb;
    const uint32_t rbBaseH = sb + B_HI_B + brow * 400 + bkb;
    const uint32_t rbBaseL = sb + B_LO_B + brow * 400 + bkb;

    float acc[2][8][4];
    #pragma unroll
    for (int mt = 0; mt < 2; mt++)
        #pragma unroll
        for (int nt = 0; nt < 8; nt++)
            #pragma unroll
            for (int i = 0; i < 4; i++) acc[mt][nt][i] = 0.f;

    for (int dy = 0; dy < 3; dy++) {
        const int gh = h - 1 + dy;
        const bool ghok = ((unsigned)gh < 256u);
        const size_t rowbase = ((size_t)(b * 256 + gh)) * 256;

        // ---- stage A: 130 rows x 64 ci, hi/lo (1040 16B-chunks each) ----
        #pragma unroll
        for (int sp = 0; sp < 2; sp++) {
            const __nv_bfloat16* src = sp ? g_xlo : g_xhi;
            char* dst = smem + (sp ? A_LO_B : A_HI_B);
            for (int idx = tid; idx < 1040; idx += 128) {
                int r = idx >> 3;             // 0..129
                int c = idx & 7;              // 8-ci chunk
                int gw = w0 - 1 + r;
                uint4 v = make_uint4(0u, 0u, 0u, 0u);
                if (ghok && (unsigned)gw < 256u)
                    v = *(const uint4*)(src + (rowbase + gw) * 64 + c * 8);
                *(uint4*)(dst + r * 144 + c * 16) = v;
            }
        }
        // ---- stage B: 64 co x 192 k, hi/lo (1536 16B-chunks each) ----
        #pragma unroll
        for (int sp = 0; sp < 2; sp++) {
            const __nv_bfloat16* src = (sp ? g_wlo : g_whi) + dy * 12288;
            char* dst = smem + (sp ? B_LO_B : B_HI_B);
            #pragma unroll
            for (int it = 0; it < 12; it++) {
                int idx = it * 128 + tid;
                int co  = idx / 24;
                int k16 = idx - co * 24;
                uint4 v = *(const uint4*)(src + co * 192 + k16 * 8);
                *(uint4*)(dst + co * 400 + k16 * 16) = v;
            }
        }
        __syncthreads();

        // ---- MMA: 3 dx x 4 ks; per step 12 ldmatrix.x4 -> 48 HMMA ----
        #pragma unroll
        for (int dx = 0; dx < 3; dx++) {
            #pragma unroll
            for (int ks = 0; ks < 4; ks++) {
                const uint32_t aoff = dx * 144 + ks * 32;
                uint32_t aH[2][4], aL[2][4];
                #pragma unroll
                for (int mt = 0; mt < 2; mt++) {
                    LDM4(aH[mt], raBaseH + mt * (16 * 144) + aoff);
                    LDM4(aL[mt], raBaseL + mt * (16 * 144) + aoff);
                }
                const uint32_t boff = dx * 128 + ks * 32;
                uint32_t bT[4][4];
                #pragma unroll
                for (int p = 0; p < 4; p++)
                    LDM4(bT[p], rbBaseH + p * (16 * 400) + boff);
                // hi*hi + lo*hi
                #pragma unroll
                for (int mt = 0; mt < 2; mt++)
                    #pragma unroll
                    for (int p = 0; p < 4; p++) {
                        mma16816(acc[mt][2*p],   aH[mt][0], aH[mt][1], aH[mt][2], aH[mt][3], bT[p][0], bT[p][1]);
                        mma16816(acc[mt][2*p+1], aH[mt][0], aH[mt][1], aH[mt][2], aH[mt][3], bT[p][2], bT[p][3]);
                        mma16816(acc[mt][2*p],   aL[mt][0], aL[mt][1], aL[mt][2], aL[mt][3], bT[p][0], bT[p][1]);
                        mma16816(acc[mt][2*p+1], aL[mt][0], aL[mt][1], aL[mt][2], aL[mt][3], bT[p][2], bT[p][3]);
                    }
                // hi*lo
                #pragma unroll
                for (int p = 0; p < 4; p++)
                    LDM4(bT[p], rbBaseL + p * (16 * 400) + boff);
                #pragma unroll
                for (int mt = 0; mt < 2; mt++)
                    #pragma unroll
                    for (int p = 0; p < 4; p++) {
                        mma16816(acc[mt][2*p],   aH[mt][0], aH[mt][1], aH[mt][2], aH[mt][3], bT[p][0], bT[p][1]);
                        mma16816(acc[mt][2*p+1], aH[mt][0], aH[mt][1], aH[mt][2], aH[mt][3], bT[p][2], bT[p][3]);
                    }
            }
        }
        __syncthreads();
    }

    // ---- epilogue: add bias, store y (NCHW) ----
    const size_t obase = (((size_t)b * 64) << 16) + (size_t)h * 256 + (size_t)w0;
    #pragma unroll
    for (int mt = 0; mt < 2; mt++) {
        const int m0 = wid * 32 + mt * 16 + gid;
        #pragma unroll
        for (int nt = 0; nt < 8; nt++) {
            const int co0 = nt * 8 + tig * 2;
            const float bv0 = __ldg(&bias[co0]);
            const float bv1 = __ldg(&bias[co0 + 1]);
            g_y[obase + ((size_t)co0       << 16) + m0]     = acc[mt][nt][0] + bv0;
            g_y[obase + ((size_t)(co0 + 1) << 16) + m0]     = acc[mt][nt][1] + bv1;
            g_y[obase + ((size_t)co0       << 16) + m0 + 8] = acc[mt][nt][2] + bv0;
            g_y[obase + ((size_t)(co0 + 1) << 16) + m0 + 8] = acc[mt][nt][3] + bv1;
        }
    }
}

// ---------------------------------------------------------------------------
// BN statistics over g_y: grid 1024 = 64 co x 16 slabs, block 256.
// ---------------------------------------------------------------------------
__global__ void stats_kernel() {
    __shared__ float sred[8][2];
    const int co   = blockIdx.x & 63;
    const int slab = blockIdx.x >> 6;
    const int tid  = threadIdx.x;

    float s1 = 0.f, s2 = 0.f;
    const int j0 = slab * 32768;
    for (int it = 0; it < 32; it++) {
        int j = j0 + (it * 256 + tid) * 4;
        int bb = j >> 16, pix = j & 65535;
        float4 v = *(const float4*)&g_y[(((size_t)bb * 64 + co) << 16) + pix];
        s1 += v.x + v.y + v.z + v.w;
        s2 = fmaf(v.x, v.x, s2); s2 = fmaf(v.y, v.y, s2);
        s2 = fmaf(v.z, v.z, s2); s2 = fmaf(v.w, v.w, s2);
    }
    #pragma unroll
    for (int o = 16; o > 0; o >>= 1) {
        s1 += __shfl_xor_sync(0xFFFFFFFFu, s1, o);
        s2 += __shfl_xor_sync(0xFFFFFFFFu, s2, o);
    }
    if ((tid & 31) == 0) { sred[tid >> 5][0] = s1; sred[tid >> 5][1] = s2; }
    __syncthreads();
    if (tid == 0) {
        float t1 = 0.f, t2 = 0.f;
        #pragma unroll
        for (int w = 0; w < 8; w++) { t1 += sred[w][0]; t2 += sred[w][1]; }
        atomicAdd(&g_sum[co],   (double)t1);
        atomicAdd(&g_sumsq[co], (double)t2);
    }
}

// ---------------------------------------------------------------------------
// BN params: training-mode batch statistics (biased variance).
// ---------------------------------------------------------------------------
__global__ void bnparam_kernel(const float* __restrict__ gamma,
                               const float* __restrict__ beta) {
    int c = threadIdx.x;
    if (c < CC) {
        const double N = (double)BB * HH * WW;
        double mean = g_sum[c] / N;
        double var  = g_sumsq[c] / N - mean * mean;
        double sc   = (double)gamma[c] / sqrt(var + 1e-5);
        g_scale[c] = (float)sc;
        g_shift[c] = (float)((double)beta[c] - mean * sc);
    }
}

// ---------------------------------------------------------------------------
// Curvature (packed f32x2): x = relu(BN(y));
// out = x (.) K5 + (x (.) D3)^2 + x  with circular wrap (lookback corr).
// ---------------------------------------------------------------------------
#define VROW 72

__global__ void __launch_bounds__(256) curv_kernel(float* __restrict__ out) {
    __shared__ float s[36 * VROW];
    __shared__ float s_k5[25], s_d3[9];

    const int tx  = threadIdx.x;
    const int ty  = threadIdx.y;
    const int tid = ty * 32 + tx;
    const int h0  = blockIdx.y * 32;
    const int w0  = blockIdx.x * 64;
    const int bc  = blockIdx.z;            // b*64 + c
    const int c   = bc & 63;

    if (tid < 25) s_k5[tid] = g_K5[tid];
    if (tid < 9)  s_d3[tid] = g_D3[tid];

    const float scale = g_scale[c];
    const float shift = g_shift[c];
    const float* yb = g_y + ((size_t)bc << 16);

    #pragma unroll
    for (int it = 0; it < 5; it++) {
        int r = ty + 8 * it;
        if (r < 36) {
            int gh = (h0 - 4 + r) & 255;
            #pragma unroll
            for (int j = 0; j < 3; j++) {
                int cc = tx + 32 * j;
                if (cc < 68) {
                    int gw = (w0 - 4 + cc) & 255;
                    float v = fmaf(yb[gh * 256 + gw], scale, shift);
                    s[r * VROW + cc] = fmaxf(v, 0.f);
                }
            }
        }
    }
    __syncthreads();

    u64 k5w[25], d3w[9];
    #pragma unroll
    for (int i = 0; i < 25; i++) { float w = s_k5[i]; k5w[i] = pk2(w, w); }
    #pragma unroll
    for (int i = 0; i < 9; i++)  { float w = s_d3[i]; d3w[i] = pk2(w, w); }

    const int cb = 2 * tx;
    #pragma unroll
    for (int rr = 0; rr < 4; rr++) {
        const int orow = ty + 8 * rr;
        u64 a = 0ull, d = 0ull, xc = 0ull;
        #pragma unroll
        for (int p = 0; p < 5; p++) {
            const float* row = s + (orow + 4 - p) * VROW + cb;
            float2 e0 = *(const float2*)(row);
            float2 e1 = *(const float2*)(row + 2);
            float2 e2 = *(const float2*)(row + 4);
            u64 q4 = pk2(e0.x, e0.y);
            u64 q3 = pk2(e0.y, e1.x);
            u64 q2 = pk2(e1.x, e1.y);
            u64 q1 = pk2(e1.y, e2.x);
            u64 q0 = pk2(e2.x, e2.y);
            ffma2(a, q0, k5w[p * 5 + 0]);
            ffma2(a, q1, k5w[p * 5 + 1]);
            ffma2(a, q2, k5w[p * 5 + 2]);
            ffma2(a, q3, k5w[p * 5 + 3]);
            ffma2(a, q4, k5w[p * 5 + 4]);
            if (p < 3) {
                ffma2(d, q0, d3w[p * 3 + 0]);
                ffma2(d, q1, d3w[p * 3 + 1]);
                ffma2(d, q2, d3w[p * 3 + 2]);
            }
            if (p == 0) xc = q0;
        }
        u64 res = fadd2(fadd2(a, fmul2(d, d)), xc);
        float r0, r1; upk2(res, r0, r1);
        *(float2*)&out[((size_t)bc << 16) + (size_t)(h0 + orow) * 256 + w0 + cb]
            = make_float2(r0, r1);
    }
}

// ---------------------------------------------------------------------------
// Launch. Inputs: feature_map, conv_w, conv_b, bn_gamma, bn_beta, filt_x,
// filt_y. Output: float32 [8,64,256,256].
// ---------------------------------------------------------------------------
extern "C" void kernel_launch(void* const* d_in, const int* in_sizes, int n_in,
                              void* d_out, int out_size) {
    const float* feat   = (const float*)d_in[0];
    const float* conv_w = (const float*)d_in[1];
    const float* conv_b = (const float*)d_in[2];
    const float* gamma  = (const float*)d_in[3];
    const float* beta   = (const float*)d_in[4];
    const float* fx     = (const float*)d_in[5];
    const float* fy     = (const float*)d_in[6];
    float* out = (float*)d_out;

    cudaFuncSetAttribute(conv_mma_kernel,
                         cudaFuncAttributeMaxDynamicSharedMemorySize, CONV_SMEM);

    prep_kernel<<<1, 64>>>(fx, fy);
    wsplit_kernel<<<144, 256>>>(conv_w);
    xsplit_kernel<<<2048, 256>>>(feat);
    conv_mma_kernel<<<4096, 128, CONV_SMEM>>>(conv_b);
    stats_kernel<<<1024, 256>>>();
    bnparam_kernel<<<1, 64>>>(gamma, beta);
    curv_kernel<<<dim3(4, 8, BB * CC), dim3(32, 8)>>>(out);
}